// round 16
// baseline (speedup 1.0000x reference)
#include <cuda_runtime.h>
#include <cuda_fp16.h>
#include <cstdint>
#include <math.h>

#define NTOK   8192
#define DMODEL 1024
#define DFFE   512
#define NEXP   16
#define DFFS   1024

// ---------------- scratch (device globals; no allocations) ----------------
__device__ int    d_cnt[NEXP];
__device__ int    d_lists[NEXP * NTOK];
__device__ float  d_gw[2 * NTOK];
__device__ __half d_ypart[(size_t)2 * NTOK * DMODEL];  // routed partials (fp16)
// fp16 operands
__device__ __half d_hx [(size_t)NTOK * DMODEL];
__device__ __half d_w1h[(size_t)NEXP * DFFE * DMODEL];
__device__ __half d_w3h[(size_t)NEXP * DFFE * DMODEL];
__device__ __half d_w2h[(size_t)NEXP * DMODEL * DFFE];
__device__ __half d_sw1h[(size_t)DFFS * DMODEL];
__device__ __half d_sw3h[(size_t)DFFS * DMODEL];
__device__ __half d_sw2h[(size_t)DMODEL * DFFS];
__device__ __half d_h [(size_t)2 * NTOK * DFFE];       // routed hidden (fp16)
__device__ __half d_hs[(size_t)NTOK * DFFS];           // shared hidden (fp16)

__device__ __forceinline__ float fsigmoid(float v) { return 1.f / (1.f + __expf(-v)); }
__device__ __forceinline__ uint32_t smem_u32(const void* p) {
    uint32_t a;
    asm("{ .reg .u64 t; cvta.to.shared.u64 t, %1; cvt.u32.u64 %0, t; }" : "=r"(a) : "l"(p));
    return a;
}
__device__ __forceinline__ void mma_f16(float* c, const uint32_t* a, uint32_t b0, uint32_t b1) {
    asm volatile("mma.sync.aligned.m16n8k16.row.col.f32.f16.f16.f32 "
        "{%0,%1,%2,%3}, {%4,%5,%6,%7}, {%8,%9}, {%0,%1,%2,%3};"
        : "+f"(c[0]), "+f"(c[1]), "+f"(c[2]), "+f"(c[3])
        : "r"(a[0]), "r"(a[1]), "r"(a[2]), "r"(a[3]), "r"(b0), "r"(b1));
}
__device__ __forceinline__ void ldsm4(uint32_t* r, uint32_t addr) {
    asm volatile("ldmatrix.sync.aligned.m8n8.x4.shared.b16 {%0,%1,%2,%3}, [%4];"
        : "=r"(r[0]), "=r"(r[1]), "=r"(r[2]), "=r"(r[3]) : "r"(addr));
}
__device__ __forceinline__ void cp_async16(uint32_t dst, const void* src) {
    asm volatile("cp.async.cg.shared.global [%0], [%1], 16;" :: "r"(dst), "l"(src));
}
__device__ __forceinline__ uint4 pack_h8(float4 u, float4 v) {
    uint4 o;
    half2 h0 = __floats2half2_rn(u.x, u.y);
    half2 h1 = __floats2half2_rn(u.z, u.w);
    half2 h2 = __floats2half2_rn(v.x, v.y);
    half2 h3 = __floats2half2_rn(v.z, v.w);
    o.x = *(uint32_t*)&h0; o.y = *(uint32_t*)&h1;
    o.z = *(uint32_t*)&h2; o.w = *(uint32_t*)&h3;
    return o;
}

// ---------------- smem layout: XOR-swizzled 128B rows ----------------
#define BK       64
#define NSTAGE   3
#define BUFBYTES (128 * 128)                   // 16384
#define ABUF_OFF 0
#define BBUF_OFF (NSTAGE * BUFBYTES)           // 49152
#define SLOT_OFF (2 * NSTAGE * BUFBYTES)       // 98304
#define BIAS_OFF (SLOT_OFF + 512)
#define SMEM_TOTAL (BIAS_OFF + 512)            // 99328
#define SWZ(row, c) ((uint32_t)((row) * 128 + (((c) ^ ((row) & 7)) << 4)))

// ---------------- pre: f2h (6 weight segments) + gate (+x->fp16) ----------------
struct PreArgs {
    const float* src[6];
    __half*      dst[6];
    int          blk_end[6];
};

__device__ void gate_body(int gblk, const float* __restrict__ x,
                          const float* __restrict__ gw,
                          const float* __restrict__ ebias,
                          __half* __restrict__ hx)
{
    int warp = (gblk * 256 + (int)threadIdx.x) >> 5;
    int lane = threadIdx.x & 31;
    if (warp >= NTOK) return;
    const float* xr = x + (size_t)warp * DMODEL;
    float xv[32];
#pragma unroll
    for (int j = 0; j < 32; j++) xv[j] = xr[lane + 32 * j];
    __half* hr = hx + (size_t)warp * DMODEL;
#pragma unroll
    for (int j = 0; j < 32; j++) hr[lane + 32 * j] = __float2half_rn(xv[j]);

    float logits[NEXP];
#pragma unroll
    for (int e = 0; e < NEXP; e++) {
        const float* wr = gw + e * DMODEL;
        float acc = 0.f;
#pragma unroll
        for (int j = 0; j < 32; j++) acc += xv[j] * wr[lane + 32 * j];
#pragma unroll
        for (int o = 16; o > 0; o >>= 1) acc += __shfl_xor_sync(0xffffffffu, acc, o);
        logits[e] = acc;
    }
    if (lane == 0) {
        int i0 = -1, i1 = -1;
        float v0 = -INFINITY, v1 = -INFINITY;
#pragma unroll
        for (int e = 0; e < NEXP; e++) {
            float b = logits[e] + ebias[e];
            if (b > v0) { v1 = v0; i1 = i0; v0 = b; i0 = e; }
            else if (b > v1) { v1 = b; i1 = e; }
        }
        float s0 = fsigmoid(logits[i0]);
        float s1 = fsigmoid(logits[i1]);
        float inv = 1.f / (s0 + s1 + 1e-10f);
        int p0 = atomicAdd(&d_cnt[i0], 1);
        d_lists[i0 * NTOK + p0] = warp * 2 + 0;
        d_gw[warp * 2 + 0] = s0 * inv;
        int p1 = atomicAdd(&d_cnt[i1], 1);
        d_lists[i1 * NTOK + p1] = warp * 2 + 1;
        d_gw[warp * 2 + 1] = s1 * inv;
    }
}

__global__ void pre_kernel(PreArgs args,
                           const float* __restrict__ x,
                           const float* __restrict__ gw,
                           const float* __restrict__ ebias,
                           __half* __restrict__ hx)
{
    int b = blockIdx.x;
    int f2h_total = args.blk_end[5];
    if (b >= f2h_total) {
        gate_body(b - f2h_total, x, gw, ebias, hx);
        return;
    }
    int seg = 0;
#pragma unroll
    for (int s = 0; s < 6; s++) if (b >= args.blk_end[s]) seg = s + 1;
    int b0 = (seg == 0) ? 0 : args.blk_end[seg - 1];
    size_t i = ((size_t)(b - b0) * blockDim.x + threadIdx.x) * 8;
    const float* src = args.src[seg];
    __half* dst = args.dst[seg];
    float4 a = *(const float4*)(src + i);
    float4 v = *(const float4*)(src + i + 4);
    *(uint4*)(dst + i) = pack_h8(a, v);
}

// ============ merged stage-1: dual-B (W1+W3 interleaved) + SwiGLU ============
__global__ void __launch_bounds__(256, 2)
gemm_dual_all(const __half* __restrict__ X,
              const __half* __restrict__ w1h, const __half* __restrict__ w3h,
              const float* __restrict__ b1,  const float* __restrict__ b3,
              const __half* __restrict__ sw1h, const __half* __restrict__ sw3h,
              const float* __restrict__ sb1, const float* __restrict__ sb3,
              __half* __restrict__ Hout, __half* __restrict__ HSout)
{
    const int K = DMODEL;
    int z = blockIdx.z;
    bool routed = (z < NEXP);
    int e  = routed ? z : 0;
    int m0 = blockIdx.y * 128;
    int n0 = routed ? blockIdx.x * 64 : ((z - NEXP) * 512 + blockIdx.x * 64);
    int Mv = NTOK;
    const int* list = d_lists + e * NTOK;
    if (routed) { Mv = d_cnt[e]; if (m0 >= Mv) return; }

    const __half* W1 = routed ? (w1h + (size_t)e * DFFE * K) : sw1h;
    const __half* W3 = routed ? (w3h + (size_t)e * DFFE * K) : sw3h;
    const float*  B1 = routed ? (b1 + (size_t)e * DFFE) : sb1;
    const float*  B3 = routed ? (b3 + (size_t)e * DFFE) : sb3;
    __half* Out = routed ? Hout : HSout;
    int ldo = routed ? DFFE : DFFS;

    extern __shared__ char smem[];
    uint32_t sbase = smem_u32(smem);
    int*   sslot = (int*)(smem + SLOT_OFF);
    float* sB1   = (float*)(smem + BIAS_OFF);
    float* sB3   = sB1 + 64;

    int tid = threadIdx.x;
    if (tid < 128) {
        int m = m0 + tid;
        sslot[tid] = routed ? list[m < Mv ? m : Mv - 1] : m;
    } else {
        int j = tid - 128;
        if (j < 64) sB1[j] = B1[n0 + j];
        else        sB3[j - 64] = B3[n0 + j - 64];
    }
    __syncthreads();

    const __half* aSrc[4]; const __half* bSrc[4]; uint32_t dstOff[4];
#pragma unroll
    for (int i = 0; i < 4; i++) {
        int idx = tid + i * 256;
        int row = idx >> 3, c = idx & 7;
        int slot = sslot[row];
        int ar = routed ? (slot >> 1) : slot;
        aSrc[i] = X + (size_t)ar * K + c * 8;
        int wn_r = row >> 6, half = (row >> 5) & 1, sub = row & 31;
        const __half* Wsel = half ? W3 : W1;
        bSrc[i] = Wsel + (size_t)(n0 + wn_r * 32 + sub) * K + c * 8;
        dstOff[i] = SWZ(row, c);
    }

    int wid = tid >> 5, lane = tid & 31;
    int wm = wid & 3, wn = wid >> 2;
    int lr = lane >> 2, lc = lane & 3;
    int mat = lane >> 3, rr = lane & 7;
    uint32_t Fsw = (uint32_t)rr << 4;
    uint32_t cA = (uint32_t)(mat >> 1) << 4;
    uint32_t cB = (uint32_t)(mat & 1) << 4;

    uint32_t aRowB[2], bRowB[4];
#pragma unroll
    for (int mf = 0; mf < 2; mf++)
        aRowB[mf] = (uint32_t)((wm * 32 + mf * 16 + (mat & 1) * 8 + rr) * 128);
#pragma unroll
    for (int fp = 0; fp < 4; fp++)
        bRowB[fp] = (uint32_t)(BBUF_OFF - ABUF_OFF + (wn * 64 + fp * 16 + (mat >> 1) * 8 + rr) * 128);

    float acc[2][8][4] = {};
    const int T = K / BK;

    auto issue_tile = [&](int t) {
        int buf = t % NSTAGE;
        uint32_t aB = sbase + ABUF_OFF + buf * BUFBYTES;
        uint32_t bB = sbase + BBUF_OFF + buf * BUFBYTES;
        int k0 = t * BK;
#pragma unroll
        for (int i = 0; i < 4; i++) {
            cp_async16(aB + dstOff[i], aSrc[i] + k0);
            cp_async16(bB + dstOff[i], bSrc[i] + k0);
        }
        asm volatile("cp.async.commit_group;" ::: "memory");
    };

    issue_tile(0);
    issue_tile(1);

    for (int t = 0; t < T; t++) {
        asm volatile("cp.async.wait_group 1;" ::: "memory");
        __syncthreads();
        // issue next tile BEFORE compute: buffer (t+2)%3 == (t-1)%3, whose last
        // consumer was compute(t-1), completed by all threads at this sync.
        if (t + 2 < T) {
            issue_tile(t + 2);
        } else {
            asm volatile("cp.async.commit_group;" ::: "memory");
        }
        uint32_t abuf = sbase + ABUF_OFF + (t % NSTAGE) * BUFBYTES;
#pragma unroll
        for (int kk = 0; kk < 4; kk++) {
            uint32_t offA = (((uint32_t)kk << 5) | cA) ^ Fsw;
            uint32_t offB = (((uint32_t)kk << 5) | cB) ^ Fsw;
            uint32_t a[2][4];
            ldsm4(a[0], abuf + aRowB[0] + offA);
            ldsm4(a[1], abuf + aRowB[1] + offA);
#pragma unroll
            for (int fp = 0; fp < 4; fp++) {
                uint32_t b[4];
                ldsm4(b, abuf + bRowB[fp] + offB);
                mma_f16(acc[0][2 * fp],     a[0], b[0], b[1]);
                mma_f16(acc[1][2 * fp],     a[1], b[0], b[1]);
                mma_f16(acc[0][2 * fp + 1], a[0], b[2], b[3]);
                mma_f16(acc[1][2 * fp + 1], a[1], b[2], b[3]);
            }
        }
    }

    // fused SwiGLU epilogue
#pragma unroll
    for (int mf = 0; mf < 2; mf++) {
#pragma unroll
        for (int half = 0; half < 2; half++) {
            int rt = wm * 32 + mf * 16 + half * 8 + lr;
            int m = m0 + rt;
            if (routed && m >= Mv) continue;
            int orow = sslot[rt];
#pragma unroll
            for (int f = 0; f < 4; f++) {
                int nl = wn * 32 + 8 * f + 2 * lc;
                float g0 = acc[mf][f][half * 2 + 0] + sB1[nl];
                float g1 = acc[mf][f][half * 2 + 1] + sB1[nl + 1];
                float u0 = acc[mf][f + 4][half * 2 + 0] + sB3[nl];
                float u1 = acc[mf][f + 4][half * 2 + 1] + sB3[nl + 1];
                float h0 = g0 * fsigmoid(g0) * u0;
                float h1 = g1 * fsigmoid(g1) * u1;
                *(half2*)(Out + (size_t)orow * ldo + n0 + nl) = __floats2half2_rn(h0, h1);
            }
        }
    }
}

// ---------------- stage-2 128x128x64 fp16 GEMM, cp.async 3-stage ----------------
template<int GATHER, int EPI>
__global__ void __launch_bounds__(256, 2)
gemm128(const __half* __restrict__ A, const __half* __restrict__ Wb,
        const float* __restrict__ bb, void* __restrict__ OutV,
        int K, int NW, int ldo)
{
    int e  = blockIdx.z;
    int m0 = blockIdx.y * 128;
    int n0 = blockIdx.x * 128;
    int Mv = NTOK;
    const int* list = d_lists + e * NTOK;
    if (GATHER != 0) { Mv = d_cnt[e]; if (m0 >= Mv) return; }
    const __half* W = Wb + (size_t)e * NW * K;

    extern __shared__ char smem[];
    uint32_t sbase = smem_u32(smem);
    int*   sslot = (int*)(smem + SLOT_OFF);
    float* sBB   = (float*)(smem + BIAS_OFF);

    int tid = threadIdx.x;
    if (tid < 128) {
        int m = m0 + tid;
        sslot[tid] = (GATHER != 0) ? list[m < Mv ? m : Mv - 1] : m;
    } else {
        sBB[tid - 128] = bb[(size_t)e * NW + n0 + (tid - 128)];
    }
    __syncthreads();

    const __half* aSrc[4]; const __half* bSrc[4]; uint32_t dstOff[4];
#pragma unroll
    for (int i = 0; i < 4; i++) {
        int idx = tid + i * 256;
        int row = idx >> 3, c = idx & 7;
        int slot = sslot[row];
        aSrc[i] = A + (size_t)slot * K + c * 8;
        bSrc[i] = W + (size_t)(n0 + row) * K + c * 8;
        dstOff[i] = SWZ(row, c);
    }

    int wid = tid >> 5, lane = tid & 31;
    int wm = wid & 3, wn = wid >> 2;
    int lr = lane >> 2, lc = lane & 3;
    int mat = lane >> 3, rr = lane & 7;
    uint32_t Fsw = (uint32_t)rr << 4;
    uint32_t cA = (uint32_t)(mat >> 1) << 4;
    uint32_t cB = (uint32_t)(mat & 1) << 4;

    uint32_t aRowB[2], bRowB[4];
#pragma unroll
    for (int mf = 0; mf < 2; mf++)
        aRowB[mf] = (uint32_t)((wm * 32 + mf * 16 + (mat & 1) * 8 + rr) * 128);
#pragma unroll
    for (int fp = 0; fp < 4; fp++)
        bRowB[fp] = (uint32_t)(BBUF_OFF - ABUF_OFF + (wn * 64 + fp * 16 + (mat >> 1) * 8 + rr) * 128);

    float acc[2][8][4] = {};
    int T = K / BK;

    auto issue_tile = [&](int t) {
        int buf = t % NSTAGE;
        uint32_t aB = sbase + ABUF_OFF + buf * BUFBYTES;
        uint32_t bB = sbase + BBUF_OFF + buf * BUFBYTES;
        int k0 = t * BK;
#pragma unroll
        for (int i = 0; i < 4; i++) {
            cp_async16(aB + dstOff[i], aSrc[i] + k0);
            cp_async16(bB + dstOff[i], bSrc[i] + k0);
        }
        asm volatile("cp.async.commit_group;" ::: "memory");
    };

    issue_tile(0);
    issue_tile(1);

    for (int t = 0; t < T; t++) {
        asm volatile("cp.async.wait_group 1;" ::: "memory");
        __syncthreads();
        if (t + 2 < T) {
            issue_tile(t + 2);
        } else {
            asm volatile("cp.async.commit_group;" ::: "memory");
        }
        uint32_t abuf = sbase + ABUF_OFF + (t % NSTAGE) * BUFBYTES;
#pragma unroll
        for (int kk = 0; kk < 4; kk++) {
            uint32_t offA = (((uint32_t)kk << 5) | cA) ^ Fsw;
            uint32_t offB = (((uint32_t)kk << 5) | cB) ^ Fsw;
            uint32_t a[2][4];
            ldsm4(a[0], abuf + aRowB[0] + offA);
            ldsm4(a[1], abuf + aRowB[1] + offA);
#pragma unroll
            for (int fp = 0; fp < 4; fp++) {
                uint32_t b[4];
                ldsm4(b, abuf + bRowB[fp] + offB);
                mma_f16(acc[0][2 * fp],     a[0], b[0], b[1]);
                mma_f16(acc[1][2 * fp],     a[1], b[0], b[1]);
                mma_f16(acc[0][2 * fp + 1], a[0], b[2], b[3]);
                mma_f16(acc[1][2 * fp + 1], a[1], b[2], b[3]);
            }
        }
    }

#pragma unroll
    for (int mf = 0; mf < 2; mf++) {
#pragma unroll
        for (int half = 0; half < 2; half++) {
            int rt = wm * 32 + mf * 16 + half * 8 + lr;
            int m = m0 + rt;
            if (GATHER != 0 && m >= Mv) continue;
            int orow = sslot[rt];
            float sc = (EPI == 1) ? d_gw[orow] : 0.f;
#pragma unroll
            for (int f = 0; f < 8; f++) {
                int nb = wn * 64 + 8 * f + 2 * lc;
                float c0 = acc[mf][f][half * 2 + 0] + sBB[nb];
                float c1 = acc[mf][f][half * 2 + 1] + sBB[nb + 1];
                if (EPI == 1) {
                    __half* O = (__half*)OutV;
                    *(half2*)(O + (size_t)orow * ldo + n0 + nb) =
                        __floats2half2_rn(c0 * sc, c1 * sc);
                } else {
                    const __half* y0 = d_ypart + (size_t)(2 * m) * DMODEL + n0 + nb;
                    const __half* y1 = y0 + DMODEL;
                    float2 a2 = __half22float2(*(const half2*)y0);
                    float2 b2 = __half22float2(*(const half2*)y1);
                    float* O = (float*)OutV;
                    *(float2*)(O + (size_t)m * ldo + n0 + nb) =
                        make_float2(c0 + a2.x + b2.x, c1 + a2.y + b2.y);
                }
            }
        }
    }
}

// ---------------- launch ----------------
extern "C" void kernel_launch(void* const* d_in, const int* in_sizes, int n_in,
                              void* d_out, int out_size)
{
    const float* x   = (const float*)d_in[0];
    const float* gw  = (const float*)d_in[1];
    const float* eb  = (const float*)d_in[2];
    const float* w1  = (const float*)d_in[3];
    const float* b1  = (const float*)d_in[4];
    const float* w3  = (const float*)d_in[5];
    const float* b3  = (const float*)d_in[6];
    const float* w2  = (const float*)d_in[7];
    const float* b2  = (const float*)d_in[8];
    const float* sw1 = (const float*)d_in[9];
    const float* sb1 = (const float*)d_in[10];
    const float* sw3 = (const float*)d_in[11];
    const float* sb3 = (const float*)d_in[12];
    const float* sw2 = (const float*)d_in[13];
    const float* sb2 = (const float*)d_in[14];
    float* out = (float*)d_out;

    int*    cnt_p; cudaGetSymbolAddress((void**)&cnt_p, d_cnt);
    __half* yp_p;  cudaGetSymbolAddress((void**)&yp_p,  d_ypart);
    __half* hx_p;  cudaGetSymbolAddress((void**)&hx_p,  d_hx);
    __half* w1h_p; cudaGetSymbolAddress((void**)&w1h_p, d_w1h);
    __half* w3h_p; cudaGetSymbolAddress((void**)&w3h_p, d_w3h);
    __half* w2h_p; cudaGetSymbolAddress((void**)&w2h_p, d_w2h);
    __half* sw1h_p; cudaGetSymbolAddress((void**)&sw1h_p, d_sw1h);
    __half* sw3h_p; cudaGetSymbolAddress((void**)&sw3h_p, d_sw3h);
    __half* sw2h_p; cudaGetSymbolAddress((void**)&sw2h_p, d_sw2h);
    __half* h_p;   cudaGetSymbolAddress((void**)&h_p,   d_h);
    __half* hs_p;  cudaGetSymbolAddress((void**)&hs_p,  d_hs);

    cudaFuncSetAttribute(gemm_dual_all, cudaFuncAttributeMaxDynamicSharedMemorySize, SMEM_TOTAL);
    cudaFuncSetAttribute(gemm128<2,1>, cudaFuncAttributeMaxDynamicSharedMemorySize, SMEM_TOTAL);
    cudaFuncSetAttribute(gemm128<0,2>, cudaFuncAttributeMaxDynamicSharedMemorySize, SMEM_TOTAL);

    cudaMemsetAsync(cnt_p, 0, NEXP * sizeof(int));

    // pre: f2h of 6 weight tensors + gate (x->fp16 fused into gate)
    {
        const int BW  = (int)(((size_t)NEXP * DFFE * DMODEL) / 2048); // 4096
        const int BSW = (int)(((size_t)DFFS * DMODEL) / 2048);        // 512
        PreArgs a;
        a.src[0] = w1;  a.dst[0] = w1h_p;
        a.src[1] = w3;  a.dst[1] = w3h_p;
        a.src[2] = w2;  a.dst[2] = w2h_p;
        a.src[3] = sw1; a.dst[3] = sw1h_p;
        a.src[4] = sw3; a.dst[4] = sw3h_p;
        a.src[5] = sw2; a.dst[5] = sw2h_p;
        int acc = 0;
        int blks[6] = {BW, BW, BW, BSW, BSW, BSW};
        for (int s = 0; s < 6; s++) { acc += blks[s]; a.blk_end[s] = acc; }
        int gate_blocks = (NTOK * 32) / 256;   // 1024
        pre_kernel<<<acc + gate_blocks, 256>>>(a, x, gw, eb, hx_p);
    }

    // merged stage 1 (routed z=0..15, shared z=16..17)
    gemm_dual_all<<<dim3(DFFE / 64, NTOK / 128, NEXP + 2), 256, SMEM_TOTAL>>>(
        hx_p, w1h_p, w3h_p, b1, b3, sw1h_p, sw3h_p, sb1, sb3, h_p, hs_p);

    // routed stage 2: ypart[slot] = (h@W2^T + b2) * gate_w -> fp16
    gemm128<2,1><<<dim3(DMODEL / 128, NTOK / 128, NEXP), 256, SMEM_TOTAL>>>(
        h_p, w2h_p, b2, yp_p, DFFE, DMODEL, DMODEL);

    // shared stage 2 + combine: out = hs@sW2^T + sb2 + ypart[2m] + ypart[2m+1]
    gemm128<0,2><<<dim3(DMODEL / 128, NTOK / 128, 1), 256, SMEM_TOTAL>>>(
        hs_p, sw2h_p, sb2, out, DMODEL, DMODEL, DMODEL);
}

// round 17
// speedup vs baseline: 1.0787x; 1.0787x over previous
#include <cuda_runtime.h>
#include <cuda_fp16.h>
#include <cstdint>
#include <math.h>

#define NTOK   8192
#define DMODEL 1024
#define DFFE   512
#define NEXP   16
#define DFFS   1024

// ---------------- scratch (device globals; no allocations) ----------------
__device__ int    d_cnt[NEXP];
__device__ int    d_lists[NEXP * NTOK];
__device__ float  d_gw[2 * NTOK];
__device__ __half d_ypart[(size_t)2 * NTOK * DMODEL];  // routed partials (fp16)
// fp16 operands
__device__ __half d_hx [(size_t)NTOK * DMODEL];
__device__ __half d_w1h[(size_t)NEXP * DFFE * DMODEL];
__device__ __half d_w3h[(size_t)NEXP * DFFE * DMODEL];
__device__ __half d_w2h[(size_t)NEXP * DMODEL * DFFE];
__device__ __half d_sw1h[(size_t)DFFS * DMODEL];
__device__ __half d_sw3h[(size_t)DFFS * DMODEL];
__device__ __half d_sw2h[(size_t)DMODEL * DFFS];
__device__ __half d_h [(size_t)2 * NTOK * DFFE];       // routed hidden (fp16)
__device__ __half d_hs[(size_t)NTOK * DFFS];           // shared hidden (fp16)

__device__ __forceinline__ float fsigmoid(float v) { return 1.f / (1.f + __expf(-v)); }
__device__ __forceinline__ uint32_t smem_u32(const void* p) {
    uint32_t a;
    asm("{ .reg .u64 t; cvta.to.shared.u64 t, %1; cvt.u32.u64 %0, t; }" : "=r"(a) : "l"(p));
    return a;
}
__device__ __forceinline__ void mma_f16(float* c, const uint32_t* a, uint32_t b0, uint32_t b1) {
    asm volatile("mma.sync.aligned.m16n8k16.row.col.f32.f16.f16.f32 "
        "{%0,%1,%2,%3}, {%4,%5,%6,%7}, {%8,%9}, {%0,%1,%2,%3};"
        : "+f"(c[0]), "+f"(c[1]), "+f"(c[2]), "+f"(c[3])
        : "r"(a[0]), "r"(a[1]), "r"(a[2]), "r"(a[3]), "r"(b0), "r"(b1));
}
__device__ __forceinline__ void ldsm4(uint32_t* r, uint32_t addr) {
    asm volatile("ldmatrix.sync.aligned.m8n8.x4.shared.b16 {%0,%1,%2,%3}, [%4];"
        : "=r"(r[0]), "=r"(r[1]), "=r"(r[2]), "=r"(r[3]) : "r"(addr));
}
__device__ __forceinline__ void cp_async16(uint32_t dst, const void* src) {
    asm volatile("cp.async.cg.shared.global [%0], [%1], 16;" :: "r"(dst), "l"(src));
}
__device__ __forceinline__ uint4 pack_h8(float4 u, float4 v) {
    uint4 o;
    half2 h0 = __floats2half2_rn(u.x, u.y);
    half2 h1 = __floats2half2_rn(u.z, u.w);
    half2 h2 = __floats2half2_rn(v.x, v.y);
    half2 h3 = __floats2half2_rn(v.z, v.w);
    o.x = *(uint32_t*)&h0; o.y = *(uint32_t*)&h1;
    o.z = *(uint32_t*)&h2; o.w = *(uint32_t*)&h3;
    return o;
}

// ---------------- smem layout: XOR-swizzled 128B rows ----------------
#define BK       64
#define NSTAGE   3
#define BUFBYTES (128 * 128)                   // 16384
#define ABUF_OFF 0
#define BBUF_OFF (NSTAGE * BUFBYTES)           // 49152
#define SLOT_OFF (2 * NSTAGE * BUFBYTES)       // 98304
#define BIAS_OFF (SLOT_OFF + 512)
#define SMEM_TOTAL (BIAS_OFF + 512)            // 99328
#define SWZ(row, c) ((uint32_t)((row) * 128 + (((c) ^ ((row) & 7)) << 4)))

// ---------------- pre: f2h (6 weight segments, 4096 elems/block) + gate ----------------
struct PreArgs {
    const float* src[6];
    __half*      dst[6];
    int          blk_end[6];
};

__device__ void gate_body(int gblk, const float* __restrict__ x,
                          const float* __restrict__ gw,
                          const float* __restrict__ ebias,
                          __half* __restrict__ hx)
{
    int warp = (gblk * 256 + (int)threadIdx.x) >> 5;
    int lane = threadIdx.x & 31;
    if (warp >= NTOK) return;
    const float* xr = x + (size_t)warp * DMODEL;
    float xv[32];
#pragma unroll
    for (int j = 0; j < 32; j++) xv[j] = xr[lane + 32 * j];
    __half* hr = hx + (size_t)warp * DMODEL;
#pragma unroll
    for (int j = 0; j < 32; j++) hr[lane + 32 * j] = __float2half_rn(xv[j]);

    float logits[NEXP];
#pragma unroll
    for (int e = 0; e < NEXP; e++) {
        const float* wr = gw + e * DMODEL;
        float acc = 0.f;
#pragma unroll
        for (int j = 0; j < 32; j++) acc += xv[j] * wr[lane + 32 * j];
#pragma unroll
        for (int o = 16; o > 0; o >>= 1) acc += __shfl_xor_sync(0xffffffffu, acc, o);
        logits[e] = acc;
    }
    if (lane == 0) {
        int i0 = -1, i1 = -1;
        float v0 = -INFINITY, v1 = -INFINITY;
#pragma unroll
        for (int e = 0; e < NEXP; e++) {
            float b = logits[e] + ebias[e];
            if (b > v0) { v1 = v0; i1 = i0; v0 = b; i0 = e; }
            else if (b > v1) { v1 = b; i1 = e; }
        }
        float s0 = fsigmoid(logits[i0]);
        float s1 = fsigmoid(logits[i1]);
        float inv = 1.f / (s0 + s1 + 1e-10f);
        int p0 = atomicAdd(&d_cnt[i0], 1);
        d_lists[i0 * NTOK + p0] = warp * 2 + 0;
        d_gw[warp * 2 + 0] = s0 * inv;
        int p1 = atomicAdd(&d_cnt[i1], 1);
        d_lists[i1 * NTOK + p1] = warp * 2 + 1;
        d_gw[warp * 2 + 1] = s1 * inv;
    }
}

__global__ void pre_kernel(PreArgs args,
                           const float* __restrict__ x,
                           const float* __restrict__ gw,
                           const float* __restrict__ ebias,
                           __half* __restrict__ hx)
{
    int b = blockIdx.x;
    int f2h_total = args.blk_end[5];
    if (b >= f2h_total) {
        gate_body(b - f2h_total, x, gw, ebias, hx);
        return;
    }
    int seg = 0;
#pragma unroll
    for (int s = 0; s < 6; s++) if (b >= args.blk_end[s]) seg = s + 1;
    int b0 = (seg == 0) ? 0 : args.blk_end[seg - 1];
    const float* src = args.src[seg];
    __half* dst = args.dst[seg];
    // 4096 elems per block; each thread converts 2 independent 8-elem chunks
    size_t base = (size_t)(b - b0) * 4096 + threadIdx.x * 8;
    float4 a0 = *(const float4*)(src + base);
    float4 v0 = *(const float4*)(src + base + 4);
    float4 a1 = *(const float4*)(src + base + 2048);
    float4 v1 = *(const float4*)(src + base + 2052);
    *(uint4*)(dst + base)        = pack_h8(a0, v0);
    *(uint4*)(dst + base + 2048) = pack_h8(a1, v1);
}

// ============ merged stage-1: dual-B (W1+W3 interleaved) + SwiGLU ============
__global__ void __launch_bounds__(256, 2)
gemm_dual_all(const __half* __restrict__ X,
              const __half* __restrict__ w1h, const __half* __restrict__ w3h,
              const float* __restrict__ b1,  const float* __restrict__ b3,
              const __half* __restrict__ sw1h, const __half* __restrict__ sw3h,
              const float* __restrict__ sb1, const float* __restrict__ sb3,
              __half* __restrict__ Hout, __half* __restrict__ HSout)
{
    const int K = DMODEL;
    int z = blockIdx.z;
    bool routed = (z < NEXP);
    int e  = routed ? z : 0;
    int m0 = blockIdx.y * 128;
    int n0 = routed ? blockIdx.x * 64 : ((z - NEXP) * 512 + blockIdx.x * 64);
    int Mv = NTOK;
    const int* list = d_lists + e * NTOK;
    if (routed) { Mv = d_cnt[e]; if (m0 >= Mv) return; }

    const __half* W1 = routed ? (w1h + (size_t)e * DFFE * K) : sw1h;
    const __half* W3 = routed ? (w3h + (size_t)e * DFFE * K) : sw3h;
    const float*  B1 = routed ? (b1 + (size_t)e * DFFE) : sb1;
    const float*  B3 = routed ? (b3 + (size_t)e * DFFE) : sb3;
    __half* Out = routed ? Hout : HSout;
    int ldo = routed ? DFFE : DFFS;

    extern __shared__ char smem[];
    uint32_t sbase = smem_u32(smem);
    int*   sslot = (int*)(smem + SLOT_OFF);
    float* sB1   = (float*)(smem + BIAS_OFF);
    float* sB3   = sB1 + 64;

    int tid = threadIdx.x;
    if (tid < 128) {
        int m = m0 + tid;
        sslot[tid] = routed ? list[m < Mv ? m : Mv - 1] : m;
    } else {
        int j = tid - 128;
        if (j < 64) sB1[j] = B1[n0 + j];
        else        sB3[j - 64] = B3[n0 + j - 64];
    }
    __syncthreads();

    const __half* aSrc[4]; const __half* bSrc[4]; uint32_t dstOff[4];
#pragma unroll
    for (int i = 0; i < 4; i++) {
        int idx = tid + i * 256;
        int row = idx >> 3, c = idx & 7;
        int slot = sslot[row];
        int ar = routed ? (slot >> 1) : slot;
        aSrc[i] = X + (size_t)ar * K + c * 8;
        int wn_r = row >> 6, half = (row >> 5) & 1, sub = row & 31;
        const __half* Wsel = half ? W3 : W1;
        bSrc[i] = Wsel + (size_t)(n0 + wn_r * 32 + sub) * K + c * 8;
        dstOff[i] = SWZ(row, c);
    }

    int wid = tid >> 5, lane = tid & 31;
    int wm = wid & 3, wn = wid >> 2;
    int lr = lane >> 2, lc = lane & 3;
    int mat = lane >> 3, rr = lane & 7;
    uint32_t Fsw = (uint32_t)rr << 4;
    uint32_t cA = (uint32_t)(mat >> 1) << 4;
    uint32_t cB = (uint32_t)(mat & 1) << 4;

    uint32_t aRowB[2], bRowB[4];
#pragma unroll
    for (int mf = 0; mf < 2; mf++)
        aRowB[mf] = (uint32_t)((wm * 32 + mf * 16 + (mat & 1) * 8 + rr) * 128);
#pragma unroll
    for (int fp = 0; fp < 4; fp++)
        bRowB[fp] = (uint32_t)(BBUF_OFF - ABUF_OFF + (wn * 64 + fp * 16 + (mat >> 1) * 8 + rr) * 128);

    float acc[2][8][4] = {};
    const int T = K / BK;

    auto issue_tile = [&](int t) {
        int buf = t % NSTAGE;
        uint32_t aB = sbase + ABUF_OFF + buf * BUFBYTES;
        uint32_t bB = sbase + BBUF_OFF + buf * BUFBYTES;
        int k0 = t * BK;
#pragma unroll
        for (int i = 0; i < 4; i++) {
            cp_async16(aB + dstOff[i], aSrc[i] + k0);
            cp_async16(bB + dstOff[i], bSrc[i] + k0);
        }
        asm volatile("cp.async.commit_group;" ::: "memory");
    };

    issue_tile(0);
    issue_tile(1);

    for (int t = 0; t < T; t++) {
        asm volatile("cp.async.wait_group 1;" ::: "memory");
        __syncthreads();
        uint32_t abuf = sbase + ABUF_OFF + (t % NSTAGE) * BUFBYTES;
#pragma unroll
        for (int kk = 0; kk < 4; kk++) {
            uint32_t offA = (((uint32_t)kk << 5) | cA) ^ Fsw;
            uint32_t offB = (((uint32_t)kk << 5) | cB) ^ Fsw;
            uint32_t a[2][4];
            ldsm4(a[0], abuf + aRowB[0] + offA);
            ldsm4(a[1], abuf + aRowB[1] + offA);
#pragma unroll
            for (int fp = 0; fp < 4; fp++) {
                uint32_t b[4];
                ldsm4(b, abuf + bRowB[fp] + offB);
                mma_f16(acc[0][2 * fp],     a[0], b[0], b[1]);
                mma_f16(acc[1][2 * fp],     a[1], b[0], b[1]);
                mma_f16(acc[0][2 * fp + 1], a[0], b[2], b[3]);
                mma_f16(acc[1][2 * fp + 1], a[1], b[2], b[3]);
            }
        }
        if (t + 2 < T) {
            issue_tile(t + 2);
        } else {
            asm volatile("cp.async.commit_group;" ::: "memory");
        }
    }

    // fused SwiGLU epilogue
#pragma unroll
    for (int mf = 0; mf < 2; mf++) {
#pragma unroll
        for (int half = 0; half < 2; half++) {
            int rt = wm * 32 + mf * 16 + half * 8 + lr;
            int m = m0 + rt;
            if (routed && m >= Mv) continue;
            int orow = sslot[rt];
#pragma unroll
            for (int f = 0; f < 4; f++) {
                int nl = wn * 32 + 8 * f + 2 * lc;
                float g0 = acc[mf][f][half * 2 + 0] + sB1[nl];
                float g1 = acc[mf][f][half * 2 + 1] + sB1[nl + 1];
                float u0 = acc[mf][f + 4][half * 2 + 0] + sB3[nl];
                float u1 = acc[mf][f + 4][half * 2 + 1] + sB3[nl + 1];
                float h0 = g0 * fsigmoid(g0) * u0;
                float h1 = g1 * fsigmoid(g1) * u1;
                *(half2*)(Out + (size_t)orow * ldo + n0 + nl) = __floats2half2_rn(h0, h1);
            }
        }
    }
}

// ---------------- stage-2 128x128x64 fp16 GEMM, cp.async 3-stage ----------------
template<int GATHER, int EPI>
__global__ void __launch_bounds__(256, 2)
gemm128(const __half* __restrict__ A, const __half* __restrict__ Wb,
        const float* __restrict__ bb, void* __restrict__ OutV,
        int K, int NW, int ldo)
{
    int e  = blockIdx.z;
    int m0 = blockIdx.y * 128;
    int n0 = blockIdx.x * 128;
    int Mv = NTOK;
    const int* list = d_lists + e * NTOK;
    if (GATHER != 0) { Mv = d_cnt[e]; if (m0 >= Mv) return; }
    const __half* W = Wb + (size_t)e * NW * K;

    extern __shared__ char smem[];
    uint32_t sbase = smem_u32(smem);
    int*   sslot = (int*)(smem + SLOT_OFF);
    float* sBB   = (float*)(smem + BIAS_OFF);

    int tid = threadIdx.x;
    if (tid < 128) {
        int m = m0 + tid;
        sslot[tid] = (GATHER != 0) ? list[m < Mv ? m : Mv - 1] : m;
    } else {
        sBB[tid - 128] = bb[(size_t)e * NW + n0 + (tid - 128)];
    }
    __syncthreads();

    const __half* aSrc[4]; const __half* bSrc[4]; uint32_t dstOff[4];
#pragma unroll
    for (int i = 0; i < 4; i++) {
        int idx = tid + i * 256;
        int row = idx >> 3, c = idx & 7;
        int slot = sslot[row];
        aSrc[i] = A + (size_t)slot * K + c * 8;
        bSrc[i] = W + (size_t)(n0 + row) * K + c * 8;
        dstOff[i] = SWZ(row, c);
    }

    int wid = tid >> 5, lane = tid & 31;
    int wm = wid & 3, wn = wid >> 2;
    int lr = lane >> 2, lc = lane & 3;
    int mat = lane >> 3, rr = lane & 7;
    uint32_t Fsw = (uint32_t)rr << 4;
    uint32_t cA = (uint32_t)(mat >> 1) << 4;
    uint32_t cB = (uint32_t)(mat & 1) << 4;

    uint32_t aRowB[2], bRowB[4];
#pragma unroll
    for (int mf = 0; mf < 2; mf++)
        aRowB[mf] = (uint32_t)((wm * 32 + mf * 16 + (mat & 1) * 8 + rr) * 128);
#pragma unroll
    for (int fp = 0; fp < 4; fp++)
        bRowB[fp] = (uint32_t)(BBUF_OFF - ABUF_OFF + (wn * 64 + fp * 16 + (mat >> 1) * 8 + rr) * 128);

    float acc[2][8][4] = {};
    int T = K / BK;

    auto issue_tile = [&](int t) {
        int buf = t % NSTAGE;
        uint32_t aB = sbase + ABUF_OFF + buf * BUFBYTES;
        uint32_t bB = sbase + BBUF_OFF + buf * BUFBYTES;
        int k0 = t * BK;
#pragma unroll
        for (int i = 0; i < 4; i++) {
            cp_async16(aB + dstOff[i], aSrc[i] + k0);
            cp_async16(bB + dstOff[i], bSrc[i] + k0);
        }
        asm volatile("cp.async.commit_group;" ::: "memory");
    };

    issue_tile(0);
    issue_tile(1);

    for (int t = 0; t < T; t++) {
        asm volatile("cp.async.wait_group 1;" ::: "memory");
        __syncthreads();
        uint32_t abuf = sbase + ABUF_OFF + (t % NSTAGE) * BUFBYTES;
#pragma unroll
        for (int kk = 0; kk < 4; kk++) {
            uint32_t offA = (((uint32_t)kk << 5) | cA) ^ Fsw;
            uint32_t offB = (((uint32_t)kk << 5) | cB) ^ Fsw;
            uint32_t a[2][4];
            ldsm4(a[0], abuf + aRowB[0] + offA);
            ldsm4(a[1], abuf + aRowB[1] + offA);
#pragma unroll
            for (int fp = 0; fp < 4; fp++) {
                uint32_t b[4];
                ldsm4(b, abuf + bRowB[fp] + offB);
                mma_f16(acc[0][2 * fp],     a[0], b[0], b[1]);
                mma_f16(acc[1][2 * fp],     a[1], b[0], b[1]);
                mma_f16(acc[0][2 * fp + 1], a[0], b[2], b[3]);
                mma_f16(acc[1][2 * fp + 1], a[1], b[2], b[3]);
            }
        }
        if (t + 2 < T) {
            issue_tile(t + 2);
        } else {
            asm volatile("cp.async.commit_group;" ::: "memory");
        }
    }

#pragma unroll
    for (int mf = 0; mf < 2; mf++) {
#pragma unroll
        for (int half = 0; half < 2; half++) {
            int rt = wm * 32 + mf * 16 + half * 8 + lr;
            int m = m0 + rt;
            if (GATHER != 0 && m >= Mv) continue;
            int orow = sslot[rt];
            float sc = (EPI == 1) ? d_gw[orow] : 0.f;
#pragma unroll
            for (int f = 0; f < 8; f++) {
                int nb = wn * 64 + 8 * f + 2 * lc;
                float c0 = acc[mf][f][half * 2 + 0] + sBB[nb];
                float c1 = acc[mf][f][half * 2 + 1] + sBB[nb + 1];
                if (EPI == 1) {
                    __half* O = (__half*)OutV;
                    *(half2*)(O + (size_t)orow * ldo + n0 + nb) =
                        __floats2half2_rn(c0 * sc, c1 * sc);
                } else {
                    const __half* y0 = d_ypart + (size_t)(2 * m) * DMODEL + n0 + nb;
                    const __half* y1 = y0 + DMODEL;
                    float2 a2 = __half22float2(*(const half2*)y0);
                    float2 b2 = __half22float2(*(const half2*)y1);
                    float* O = (float*)OutV;
                    *(float2*)(O + (size_t)m * ldo + n0 + nb) =
                        make_float2(c0 + a2.x + b2.x, c1 + a2.y + b2.y);
                }
            }
        }
    }
}

// ---------------- launch ----------------
extern "C" void kernel_launch(void* const* d_in, const int* in_sizes, int n_in,
                              void* d_out, int out_size)
{
    const float* x   = (const float*)d_in[0];
    const float* gw  = (const float*)d_in[1];
    const float* eb  = (const float*)d_in[2];
    const float* w1  = (const float*)d_in[3];
    const float* b1  = (const float*)d_in[4];
    const float* w3  = (const float*)d_in[5];
    const float* b3  = (const float*)d_in[6];
    const float* w2  = (const float*)d_in[7];
    const float* b2  = (const float*)d_in[8];
    const float* sw1 = (const float*)d_in[9];
    const float* sb1 = (const float*)d_in[10];
    const float* sw3 = (const float*)d_in[11];
    const float* sb3 = (const float*)d_in[12];
    const float* sw2 = (const float*)d_in[13];
    const float* sb2 = (const float*)d_in[14];
    float* out = (float*)d_out;

    int*    cnt_p; cudaGetSymbolAddress((void**)&cnt_p, d_cnt);
    __half* yp_p;  cudaGetSymbolAddress((void**)&yp_p,  d_ypart);
    __half* hx_p;  cudaGetSymbolAddress((void**)&hx_p,  d_hx);
    __half* w1h_p; cudaGetSymbolAddress((void**)&w1h_p, d_w1h);
    __half* w3h_p; cudaGetSymbolAddress((void**)&w3h_p, d_w3h);
    __half* w2h_p; cudaGetSymbolAddress((void**)&w2h_p, d_w2h);
    __half* sw1h_p; cudaGetSymbolAddress((void**)&sw1h_p, d_sw1h);
    __half* sw3h_p; cudaGetSymbolAddress((void**)&sw3h_p, d_sw3h);
    __half* sw2h_p; cudaGetSymbolAddress((void**)&sw2h_p, d_sw2h);
    __half* h_p;   cudaGetSymbolAddress((void**)&h_p,   d_h);
    __half* hs_p;  cudaGetSymbolAddress((void**)&hs_p,  d_hs);

    cudaFuncSetAttribute(gemm_dual_all, cudaFuncAttributeMaxDynamicSharedMemorySize, SMEM_TOTAL);
    cudaFuncSetAttribute(gemm128<2,1>, cudaFuncAttributeMaxDynamicSharedMemorySize, SMEM_TOTAL);
    cudaFuncSetAttribute(gemm128<0,2>, cudaFuncAttributeMaxDynamicSharedMemorySize, SMEM_TOTAL);

    cudaMemsetAsync(cnt_p, 0, NEXP * sizeof(int));

    // pre: f2h of 6 weight tensors (4096 elems/block) + gate (x->fp16 fused)
    {
        const int BW  = (int)(((size_t)NEXP * DFFE * DMODEL) / 4096); // 2048
        const int BSW = (int)(((size_t)DFFS * DMODEL) / 4096);        // 256
        PreArgs a;
        a.src[0] = w1;  a.dst[0] = w1h_p;
        a.src[1] = w3;  a.dst[1] = w3h_p;
        a.src[2] = w2;  a.dst[2] = w2h_p;
        a.src[3] = sw1; a.dst[3] = sw1h_p;
        a.src[4] = sw3; a.dst[4] = sw3h_p;
        a.src[5] = sw2; a.dst[5] = sw2h_p;
        int acc = 0;
        int blks[6] = {BW, BW, BW, BSW, BSW, BSW};
        for (int s = 0; s < 6; s++) { acc += blks[s]; a.blk_end[s] = acc; }
        int gate_blocks = (NTOK * 32) / 256;   // 1024
        pre_kernel<<<acc + gate_blocks, 256>>>(a, x, gw, eb, hx_p);
    }

    // merged stage 1 (routed z=0..15, shared z=16..17)
    gemm_dual_all<<<dim3(DFFE / 64, NTOK / 128, NEXP + 2), 256, SMEM_TOTAL>>>(
        hx_p, w1h_p, w3h_p, b1, b3, sw1h_p, sw3h_p, sb1, sb3, h_p, hs_p);

    // routed stage 2: ypart[slot] = (h@W2^T + b2) * gate_w -> fp16
    gemm128<2,1><<<dim3(DMODEL / 128, NTOK / 128, NEXP), 256, SMEM_TOTAL>>>(
        h_p, w2h_p, b2, yp_p, DFFE, DMODEL, DMODEL);

    // shared stage 2 + combine: out = hs@sW2^T + sb2 + ypart[2m] + ypart[2m+1]
    gemm128<0,2><<<dim3(DMODEL / 128, NTOK / 128, 1), 256, SMEM_TOTAL>>>(
        hs_p, sw2h_p, sb2, out, DMODEL, DMODEL, DMODEL);
}